// round 3
// baseline (speedup 1.0000x reference)
#include <cuda_runtime.h>
#include <cuda_bf16.h>
#include <cstdint>

// Problem constants
#define BB 8
#define SS 2048
#define DD 512
#define II 2048

// Tiling
#define TILE_S 64          // s rows per CTA tile
#define TILE_I 64          // i cols per CTA
#define KC 32              // K chunk
#define NKT (DD / KC)      // 16 K chunks
#define NST (SS / TILE_S)  // 32 s tiles
#define SX 36              // padded smem stride for x/W tiles (float units)
#define SA 65              // padded smem stride for a/c scan tiles (odd)

// tf32-rounded scratch copies of inputs
__device__ float g_x[(size_t)BB * SS * DD];
__device__ float g_wa[(size_t)II * DD];
__device__ float g_wi[(size_t)II * DD];

__device__ __forceinline__ float ex2f_(float x) {
    float y; asm("ex2.approx.f32 %0, %1;" : "=f"(y) : "f"(x)); return y;
}
__device__ __forceinline__ float rcpf_(float x) {
    float y; asm("rcp.approx.f32 %0, %1;" : "=f"(y) : "f"(x)); return y;
}
__device__ __forceinline__ float sqrtf_(float x) {
    float y; asm("sqrt.approx.f32 %0, %1;" : "=f"(y) : "f"(x)); return y;
}
__device__ __forceinline__ float sigmoidf_(float x) {
    return rcpf_(1.0f + ex2f_(-1.44269504f * x));
}
__device__ __forceinline__ float cvt_tf32(float x) {
    float y; asm("cvt.rna.tf32.f32 %0, %1;" : "=f"(y) : "f"(x)); return y;
}

__device__ __forceinline__ void cp16(uint32_t dst, const float* src) {
    asm volatile("cp.async.cg.shared.global [%0], [%1], 16;\n" :: "r"(dst), "l"(src));
}

__device__ __forceinline__ void mma_tf32(float* c, const float* a, float b0, float b1) {
    asm volatile(
        "mma.sync.aligned.m16n8k8.row.col.f32.tf32.tf32.f32 "
        "{%0,%1,%2,%3}, {%4,%5,%6,%7}, {%8,%9}, {%0,%1,%2,%3};\n"
        : "+f"(c[0]), "+f"(c[1]), "+f"(c[2]), "+f"(c[3])
        : "r"(__float_as_uint(a[0])), "r"(__float_as_uint(a[1])),
          "r"(__float_as_uint(a[2])), "r"(__float_as_uint(a[3])),
          "r"(__float_as_uint(b0)), "r"(__float_as_uint(b1)));
}

// Prepass: round x, Wa, Wi to tf32 (rna) into device scratch
__global__ void prepass_kernel(const float* __restrict__ x,
                               const float* __restrict__ wa,
                               const float* __restrict__ wi) {
    int i = blockIdx.x * blockDim.x + threadIdx.x;  // grid exactly covers x
    g_x[i] = cvt_tf32(x[i]);
    if (i < II * DD) {
        g_wa[i] = cvt_tf32(wa[i]);
        g_wi[i] = cvt_tf32(wi[i]);
    }
}

// smem layout (floats):
//  xs  : 2 * 64 * SX   = 4608
//  was : 2 * 64 * SX   = 4608
//  wis : 2 * 64 * SX   = 4608
//  a_s : 64 * SA       = 4160
//  c_s : 64 * SA       = 4160
#define SMEM_FLOATS (2*TILE_S*SX + 2*TILE_I*SX + 2*TILE_I*SX + 2*TILE_S*SA)
#define SMEM_BYTES  (SMEM_FLOATS * 4)

__global__ __launch_bounds__(256, 2)
void fused_gru_kernel(const float* __restrict__ ba,
                      const float* __restrict__ bi,
                      const float* __restrict__ gate,
                      float* __restrict__ out) {
    extern __shared__ float sm[];
    float* xs  = sm;                       // [2][64][SX]
    float* was = xs  + 2 * TILE_S * SX;    // [2][64][SX]
    float* wis = was + 2 * TILE_I * SX;    // [2][64][SX]
    float* a_s = wis + 2 * TILE_I * SX;    // [64][SA]
    float* c_s = a_s + TILE_S * SA;        // [64][SA]

    const int tid  = threadIdx.x;
    const int lane = tid & 31;
    const int w    = tid >> 5;       // 0..7
    const int wm   = w >> 2;         // 0..1 : s-offset wm*32
    const int wn   = w & 3;          // 0..3 : i-offset wn*16
    const int g    = lane >> 2;      // 0..7
    const int tg   = lane & 3;       // 0..3

    const int b  = blockIdx.x >> 5;      // 8 batches
    const int it = blockIdx.x & 31;      // 32 i-tiles
    const int i0 = it * TILE_I;

    // Per-thread column constants: 2 ntiles x 2 (frag col parity)
    float alpr[2][2], bar[2][2], bir[2][2];
#pragma unroll
    for (int nt = 0; nt < 2; ++nt) {
#pragma unroll
        for (int j = 0; j < 2; ++j) {
            int ii = i0 + wn * 16 + nt * 8 + tg * 2 + j;
            alpr[nt][j] = sigmoidf_(gate[ii]);
            bar[nt][j]  = ba[ii];
            bir[nt][j]  = bi[ii];
        }
    }

    const float* xg  = g_x  + (size_t)b * SS * DD;
    const float* wag = g_wa + (size_t)i0 * DD;
    const float* wig = g_wi + (size_t)i0 * DD;

    uint32_t xs_u  = (uint32_t)__cvta_generic_to_shared(xs);
    uint32_t was_u = (uint32_t)__cvta_generic_to_shared(was);
    uint32_t wis_u = (uint32_t)__cvta_generic_to_shared(wis);

    float h = 0.0f;  // scan state (tid < TILE_I)

    // ---- prefetch s-tile 0, chunk 0 into stage 0 ----
    {
#pragma unroll
        for (int j = 0; j < 2; ++j) {  // x: 64 rows x 8 float4 = 512
            int idx = tid + j * 256;
            int r = idx >> 3, c4 = idx & 7;
            cp16(xs_u + (r * SX + c4 * 4) * 4, xg + (size_t)r * DD + c4 * 4);
        }
#pragma unroll
        for (int j = 0; j < 2; ++j) {  // W: 512 float4 each
            int idx = tid + j * 256;
            int r = idx >> 3, c4 = idx & 7;
            size_t go = (size_t)r * DD + c4 * 4;
            uint32_t so = (r * SX + c4 * 4) * 4;
            cp16(was_u + so, wag + go);
            cp16(wis_u + so, wig + go);
        }
        asm volatile("cp.async.commit_group;\n");
    }

    for (int st = 0; st < NST; ++st) {
        const int s0 = st * TILE_S;

        float acc[2][2][2][4];  // [gemm][mtile][ntile][frag]
#pragma unroll
        for (int gm = 0; gm < 2; ++gm)
#pragma unroll
            for (int mt = 0; mt < 2; ++mt)
#pragma unroll
                for (int nt = 0; nt < 2; ++nt)
#pragma unroll
                    for (int f = 0; f < 4; ++f) acc[gm][mt][nt][f] = 0.0f;

        // ---- K loop ----
        for (int kt = 0; kt < NKT; ++kt) {
            __syncthreads();  // prior stage consumed before refill; also orders scan->reuse
            if (kt + 1 < NKT) {
                const int stg = (kt + 1) & 1;
#pragma unroll
                for (int j = 0; j < 2; ++j) {
                    int idx = tid + j * 256;
                    int r = idx >> 3, c4 = idx & 7;
                    cp16(xs_u + (stg * TILE_S * SX + r * SX + c4 * 4) * 4,
                         xg + (size_t)(s0 + r) * DD + (kt + 1) * KC + c4 * 4);
                }
#pragma unroll
                for (int j = 0; j < 2; ++j) {
                    int idx = tid + j * 256;
                    int r = idx >> 3, c4 = idx & 7;
                    size_t go = (size_t)r * DD + (kt + 1) * KC + c4 * 4;
                    uint32_t so = (stg * TILE_I * SX + r * SX + c4 * 4) * 4;
                    cp16(was_u + so, wag + go);
                    cp16(wis_u + so, wig + go);
                }
                asm volatile("cp.async.commit_group;\n");
                asm volatile("cp.async.wait_group 1;\n");
            } else {
                asm volatile("cp.async.wait_group 0;\n");
            }
            __syncthreads();  // loaded data visible to all

            const int stg = kt & 1;
            const float* xst = xs  + stg * TILE_S * SX;
            const float* wat = was + stg * TILE_I * SX;
            const float* wit = wis + stg * TILE_I * SX;

#pragma unroll
            for (int k8 = 0; k8 < KC / 8; ++k8) {
                const int kb = k8 * 8;
                float afr[2][4];
#pragma unroll
                for (int mt = 0; mt < 2; ++mt) {
                    int r = wm * 32 + mt * 16;
                    afr[mt][0] = xst[(r + g) * SX + kb + tg];
                    afr[mt][1] = xst[(r + 8 + g) * SX + kb + tg];
                    afr[mt][2] = xst[(r + g) * SX + kb + tg + 4];
                    afr[mt][3] = xst[(r + 8 + g) * SX + kb + tg + 4];
                }
#pragma unroll
                for (int nt = 0; nt < 2; ++nt) {
                    int c = wn * 16 + nt * 8;
                    float b0a = wat[(c + g) * SX + kb + tg];
                    float b1a = wat[(c + g) * SX + kb + tg + 4];
                    float b0i = wit[(c + g) * SX + kb + tg];
                    float b1i = wit[(c + g) * SX + kb + tg + 4];
#pragma unroll
                    for (int mt = 0; mt < 2; ++mt) {
                        mma_tf32(acc[0][mt][nt], afr[mt], b0a, b1a);
                        mma_tf32(acc[1][mt][nt], afr[mt], b0i, b1i);
                    }
                }
            }
        }

        // ---- elementwise epilogue: regs -> a_s/c_s ----
#pragma unroll
        for (int mt = 0; mt < 2; ++mt) {
#pragma unroll
            for (int nt = 0; nt < 2; ++nt) {
#pragma unroll
                for (int f = 0; f < 4; ++f) {
                    int r   = wm * 32 + mt * 16 + g + ((f >= 2) ? 8 : 0);
                    int col = wn * 16 + nt * 8 + tg * 2 + (f & 1);
                    float pa = acc[0][mt][nt][f] + bar[nt][f & 1];
                    float pi = acc[1][mt][nt][f] + bir[nt][f & 1];
                    float rg = sigmoidf_(pa);
                    float ig = sigmoidf_(pi);
                    float ad = alpr[nt][f & 1] * ex2f_(-1.5849625007f * rg);
                    float dr = sqrtf_(fmaxf(1.0f - ad * ad, 0.0f)) * (ig * pi);
                    a_s[r * SA + col] = ad;
                    c_s[r * SA + col] = dr;
                }
            }
        }
        __syncthreads();

        // ---- prefetch next s-tile chunk 0 into stage 0 (overlaps with scan) ----
        if (st + 1 < NST) {
            const int s1 = (st + 1) * TILE_S;
#pragma unroll
            for (int j = 0; j < 2; ++j) {
                int idx = tid + j * 256;
                int r = idx >> 3, c4 = idx & 7;
                cp16(xs_u + (r * SX + c4 * 4) * 4,
                     xg + (size_t)(s1 + r) * DD + c4 * 4);
            }
#pragma unroll
            for (int j = 0; j < 2; ++j) {
                int idx = tid + j * 256;
                int r = idx >> 3, c4 = idx & 7;
                size_t go = (size_t)r * DD + c4 * 4;
                uint32_t so = (r * SX + c4 * 4) * 4;
                cp16(was_u + so, wag + go);
                cp16(wis_u + so, wig + go);
            }
            asm volatile("cp.async.commit_group;\n");
        }

        // ---- sequential scan over this s-tile ----
        if (tid < TILE_I) {
            float* op = out + ((size_t)b * SS + s0) * II + i0 + tid;
#pragma unroll 4
            for (int s = 0; s < TILE_S; ++s) {
                h = fmaf(a_s[s * SA + tid], h, c_s[s * SA + tid]);
                *op = h;
                op += II;
            }
        }
        // NOTE: no barrier here — the sync at the top of the next K loop
        // orders scan reads of a_s/c_s before the next epilogue writes.
    }
}

extern "C" void kernel_launch(void* const* d_in, const int* in_sizes, int n_in,
                              void* d_out, int out_size) {
    const float* x    = (const float*)d_in[0];
    const float* Wa   = (const float*)d_in[1];
    const float* ba   = (const float*)d_in[2];
    const float* Wi   = (const float*)d_in[3];
    const float* bi   = (const float*)d_in[4];
    const float* gate = (const float*)d_in[5];
    float* out = (float*)d_out;

    prepass_kernel<<<(BB * SS * DD) / 256, 256>>>(x, Wa, Wi);

    cudaFuncSetAttribute(fused_gru_kernel,
                         cudaFuncAttributeMaxDynamicSharedMemorySize, SMEM_BYTES);
    fused_gru_kernel<<<BB * (II / TILE_I), 256, SMEM_BYTES>>>(ba, bi, gate, out);
}

// round 7
// speedup vs baseline: 1.0525x; 1.0525x over previous
#include <cuda_runtime.h>
#include <cuda_bf16.h>
#include <cstdint>

// Problem constants
#define BB 8
#define SS 2048
#define DD 512
#define II 2048

// Tiling
#define TILE_S 64          // s rows per CTA tile
#define TILE_I 128         // i cols per CTA
#define KC 32              // K chunk
#define NKT (DD / KC)      // 16 K chunks
#define NST (SS / TILE_S)  // 32 s tiles
#define NCH (NST * NKT)    // 512 chunks total per CTA
#define SX 36              // padded smem stride for x/W tiles (floats, 144B 16B-aligned)
#define SA 132             // padded smem stride for a/c scan tiles

// tf32-rounded scratch copies of inputs
__device__ float g_x[(size_t)BB * SS * DD];
__device__ float g_wa[(size_t)II * DD];
__device__ float g_wi[(size_t)II * DD];

__device__ __forceinline__ float ex2f_(float x) {
    float y; asm("ex2.approx.f32 %0, %1;" : "=f"(y) : "f"(x)); return y;
}
__device__ __forceinline__ float rcpf_(float x) {
    float y; asm("rcp.approx.f32 %0, %1;" : "=f"(y) : "f"(x)); return y;
}
__device__ __forceinline__ float sqrtf_(float x) {
    float y; asm("sqrt.approx.f32 %0, %1;" : "=f"(y) : "f"(x)); return y;
}
__device__ __forceinline__ float sigmoidf_(float x) {
    return rcpf_(1.0f + ex2f_(-1.44269504f * x));
}
__device__ __forceinline__ float cvt_tf32(float x) {
    float y; asm("cvt.rna.tf32.f32 %0, %1;" : "=f"(y) : "f"(x)); return y;
}

__device__ __forceinline__ void cp16(uint32_t dst, const float* src) {
    asm volatile("cp.async.cg.shared.global [%0], [%1], 16;\n" :: "r"(dst), "l"(src));
}

__device__ __forceinline__ void ldsm4(uint32_t* d, uint32_t addr) {
    asm volatile("ldmatrix.sync.aligned.m8n8.x4.shared.b16 {%0,%1,%2,%3}, [%4];"
                 : "=r"(d[0]), "=r"(d[1]), "=r"(d[2]), "=r"(d[3]) : "r"(addr));
}

__device__ __forceinline__ void mma_tf32(float* c, const uint32_t* a, uint32_t b0, uint32_t b1) {
    asm volatile(
        "mma.sync.aligned.m16n8k8.row.col.f32.tf32.tf32.f32 "
        "{%0,%1,%2,%3}, {%4,%5,%6,%7}, {%8,%9}, {%0,%1,%2,%3};\n"
        : "+f"(c[0]), "+f"(c[1]), "+f"(c[2]), "+f"(c[3])
        : "r"(a[0]), "r"(a[1]), "r"(a[2]), "r"(a[3]), "r"(b0), "r"(b1));
}

// Prepass: round x, Wa, Wi to tf32 (rna) into device scratch
__global__ void prepass_kernel(const float* __restrict__ x,
                               const float* __restrict__ wa,
                               const float* __restrict__ wi) {
    int i = blockIdx.x * blockDim.x + threadIdx.x;  // grid exactly covers x
    g_x[i] = cvt_tf32(x[i]);
    if (i < II * DD) {
        g_wa[i] = cvt_tf32(wa[i]);
        g_wi[i] = cvt_tf32(wi[i]);
    }
}

// smem layout (floats):
//  xs   : 2 * 64  * SX = 4608
//  was  : 2 * 128 * SX = 9216
//  wis  : 2 * 128 * SX = 9216
//  ab   : 2 * 64  * SA = 16896   (double-buffered a)
//  cbuf : 2 * 64  * SA = 16896   (double-buffered c)
#define SMEM_FLOATS (2*TILE_S*SX + 4*TILE_I*SX + 4*TILE_S*SA)
#define SMEM_BYTES  (SMEM_FLOATS * 4)   // 227328 <= 232448 opt-in

__global__ __launch_bounds__(256, 1)
void fused_gru_kernel(const float* __restrict__ ba,
                      const float* __restrict__ bi,
                      const float* __restrict__ gate,
                      float* __restrict__ out) {
    extern __shared__ float sm[];
    float* xs   = sm;                        // [2][64][SX]
    float* was  = xs   + 2 * TILE_S * SX;    // [2][128][SX]
    float* wis  = was  + 2 * TILE_I * SX;    // [2][128][SX]
    float* ab   = wis  + 2 * TILE_I * SX;    // [2][64][SA]
    float* cbuf = ab   + 2 * TILE_S * SA;    // [2][64][SA]

    const int tid  = threadIdx.x;
    const int lane = tid & 31;
    const int w    = tid >> 5;       // 0..7
    const int wm   = w >> 2;         // 0..1 : s-offset wm*32
    const int wn   = w & 3;          // 0..3 : i-offset wn*32
    const int g    = lane >> 2;      // 0..7
    const int tg   = lane & 3;       // 0..3

    // ldmatrix lane addressing: quad q picks 8x8 tile, rr is row within tile
    const int q  = lane >> 3;        // 0..3
    const int rr = lane & 7;         // 0..7
    const int loff = ((q & 1) * 8 + rr) * SX + (q >> 1) * 4;  // floats

    const int b  = blockIdx.x >> 4;
    const int it = blockIdx.x & 15;
    const int i0 = it * TILE_I;

    // Per-thread column constants
    float alpr[4][2], bar[4][2], bir[4][2];
#pragma unroll
    for (int nt = 0; nt < 4; ++nt) {
#pragma unroll
        for (int j = 0; j < 2; ++j) {
            int ii = i0 + wn * 32 + nt * 8 + tg * 2 + j;
            alpr[nt][j] = sigmoidf_(gate[ii]);
            bar[nt][j]  = ba[ii];
            bir[nt][j]  = bi[ii];
        }
    }

    const float* xg  = g_x  + (size_t)b * SS * DD;
    const float* wag = g_wa + (size_t)i0 * DD;
    const float* wig = g_wi + (size_t)i0 * DD;

    uint32_t xs_u  = (uint32_t)__cvta_generic_to_shared(xs);
    uint32_t was_u = (uint32_t)__cvta_generic_to_shared(was);
    uint32_t wis_u = (uint32_t)__cvta_generic_to_shared(wis);

    // ldmatrix byte-offset bases (per thread), kb added per k8 step
    const uint32_t aoff0 = ((wm * 32 +  0) * SX + loff) * 4;
    const uint32_t aoff1 = ((wm * 32 + 16) * SX + loff) * 4;
    const uint32_t boff0 = ((wn * 32 +  0) * SX + loff) * 4;
    const uint32_t boff1 = ((wn * 32 + 16) * SX + loff) * 4;

    // chunk loader: global chunk index gcn in [0, NCH)
    auto issue = [&](int gcn) {
        const int ktn = gcn & (NKT - 1);
        const int stn = gcn >> 4;
        const int slot = gcn & 1;
        const int s0n = stn * TILE_S;
#pragma unroll
        for (int j = 0; j < 2; ++j) {  // x: 64 rows x 8 float4
            int idx = tid + j * 256;
            int r = idx >> 3, c4 = idx & 7;
            cp16(xs_u + (uint32_t)(slot * TILE_S * SX + r * SX + c4 * 4) * 4,
                 xg + (size_t)(s0n + r) * DD + ktn * KC + c4 * 4);
        }
#pragma unroll
        for (int j = 0; j < 4; ++j) {  // W: 128 rows x 8 float4, both gemms
            int idx = tid + j * 256;
            int r = idx >> 3, c4 = idx & 7;
            size_t go = (size_t)r * DD + ktn * KC + c4 * 4;
            uint32_t so = (uint32_t)(slot * TILE_I * SX + r * SX + c4 * 4) * 4;
            cp16(was_u + so, wag + go);
            cp16(wis_u + so, wig + go);
        }
        asm volatile("cp.async.commit_group;\n");
    };

    issue(0);

    float h = 0.0f;  // scan state (tid < TILE_I)

    for (int st = 0; st < NST; ++st) {
        float acc[2][2][4][4];  // [gemm][mtile][ntile][frag]
#pragma unroll
        for (int gm = 0; gm < 2; ++gm)
#pragma unroll
            for (int mt = 0; mt < 2; ++mt)
#pragma unroll
                for (int nt = 0; nt < 4; ++nt)
#pragma unroll
                    for (int f = 0; f < 4; ++f) acc[gm][mt][nt][f] = 0.0f;

        for (int kt = 0; kt < NKT; ++kt) {
            const int gc = st * NKT + kt;

            // current chunk's data fully arrived (own groups), then make
            // visible to all + protect the slot we are about to refill
            asm volatile("cp.async.wait_group 0;\n");
            __syncthreads();
            if (gc + 1 < NCH) issue(gc + 1);

            const int stg = gc & 1;
            const uint32_t xb  = xs_u  + (uint32_t)(stg * TILE_S * SX) * 4;
            const uint32_t wab = was_u + (uint32_t)(stg * TILE_I * SX) * 4;
            const uint32_t wib = wis_u + (uint32_t)(stg * TILE_I * SX) * 4;

#pragma unroll
            for (int k8 = 0; k8 < KC / 8; ++k8) {
                const uint32_t kb4 = k8 * 8 * 4;
                uint32_t af[2][4], bfa[2][4], bfi[2][4];
                ldsm4(af[0],  xb  + aoff0 + kb4);
                ldsm4(af[1],  xb  + aoff1 + kb4);
                ldsm4(bfa[0], wab + boff0 + kb4);  // ntiles 0,1: {b0n0,b0n1,b1n0,b1n1}
                ldsm4(bfa[1], wab + boff1 + kb4);  // ntiles 2,3
                ldsm4(bfi[0], wib + boff0 + kb4);
                ldsm4(bfi[1], wib + boff1 + kb4);
#pragma unroll
                for (int nt = 0; nt < 4; ++nt) {
                    const int p = nt >> 1, o = nt & 1;
#pragma unroll
                    for (int mt = 0; mt < 2; ++mt) {
                        mma_tf32(acc[0][mt][nt], af[mt], bfa[p][o], bfa[p][2 + o]);
                        mma_tf32(acc[1][mt][nt], af[mt], bfi[p][o], bfi[p][2 + o]);
                    }
                }
            }

            // interleaved scan of PREVIOUS s-tile (4 steps per chunk)
            if (st > 0 && tid < TILE_I) {
                const int p = (st - 1) & 1;
                const float* ap = ab   + p * TILE_S * SA;
                const float* cp = cbuf + p * TILE_S * SA;
                const int sb = kt * 4;
                float* op = out + ((size_t)b * SS + (size_t)(st - 1) * TILE_S + sb) * II + i0 + tid;
#pragma unroll
                for (int j = 0; j < 4; ++j) {
                    h = fmaf(ap[(sb + j) * SA + tid], h, cp[(sb + j) * SA + tid]);
                    op[(size_t)j * II] = h;
                }
            }
        }

        // ---- elementwise epilogue: regs -> a/c buffer (parity st&1) ----
        float* at = ab   + (st & 1) * TILE_S * SA;
        float* ct = cbuf + (st & 1) * TILE_S * SA;
#pragma unroll
        for (int mt = 0; mt < 2; ++mt) {
#pragma unroll
            for (int nt = 0; nt < 4; ++nt) {
#pragma unroll
                for (int f = 0; f < 4; ++f) {
                    int r   = wm * 32 + mt * 16 + g + ((f >= 2) ? 8 : 0);
                    int col = wn * 32 + nt * 8 + tg * 2 + (f & 1);
                    float pa = acc[0][mt][nt][f] + bar[nt][f & 1];
                    float pi = acc[1][mt][nt][f] + bir[nt][f & 1];
                    float rg = sigmoidf_(pa);
                    float ig = sigmoidf_(pi);
                    float ad = alpr[nt][f & 1] * ex2f_(-1.5849625007f * rg);
                    float dr = sqrtf_(fmaxf(1.0f - ad * ad, 0.0f)) * (ig * pi);
                    at[r * SA + col] = ad;
                    ct[r * SA + col] = dr;
                }
            }
        }
        // no barrier here: the wait+sync at the top of the next chunk orders
        // epilogue writes before the next tile's interleaved scan reads.
    }

    // ---- tail: scan the last s-tile ----
    __syncthreads();
    if (tid < TILE_I) {
        const int p = (NST - 1) & 1;
        const float* ap = ab   + p * TILE_S * SA;
        const float* cp = cbuf + p * TILE_S * SA;
        float* op = out + ((size_t)b * SS + (size_t)(NST - 1) * TILE_S) * II + i0 + tid;
#pragma unroll 4
        for (int s = 0; s < TILE_S; ++s) {
            h = fmaf(ap[s * SA + tid], h, cp[s * SA + tid]);
            *op = h;
            op += II;
        }
    }
}

extern "C" void kernel_launch(void* const* d_in, const int* in_sizes, int n_in,
                              void* d_out, int out_size) {
    const float* x    = (const float*)d_in[0];
    const float* Wa   = (const float*)d_in[1];
    const float* ba   = (const float*)d_in[2];
    const float* Wi   = (const float*)d_in[3];
    const float* bi   = (const float*)d_in[4];
    const float* gate = (const float*)d_in[5];
    float* out = (float*)d_out;

    prepass_kernel<<<(BB * SS * DD) / 256, 256>>>(x, Wa, Wi);

    cudaFuncSetAttribute(fused_gru_kernel,
                         cudaFuncAttributeMaxDynamicSharedMemorySize, SMEM_BYTES);
    fused_gru_kernel<<<BB * (II / TILE_I), 256, SMEM_BYTES>>>(ba, bi, gate, out);
}

// round 13
// speedup vs baseline: 1.0608x; 1.0079x over previous
#include <cuda_runtime.h>
#include <cstdint>

// Problem constants
#define BB 8
#define SS 2048
#define DD 512
#define II 2048

// Tiling
#define TILE_S 64           // s rows per CTA tile
#define TILE_I 128          // i cols per CTA
#define KC 32               // K chunk
#define NKT (DD / KC)       // 16 chunks per s-tile
#define NST (SS / TILE_S)   // 32 s-tiles
#define NCH (NST * NKT)     // 512 chunks per CTA
#define NSTG 3              // cp.async pipeline stages
#define SX 36               // padded smem row stride for x/W tiles (floats)
#define SA 132              // padded smem row stride for proj/scan buffers

// per-stage float counts
#define XF   (TILE_S * SX)            // 2304
#define WF   (TILE_I * SX)            // 4608
#define STGF (XF + 2 * WF)            // 11520 floats per stage
#define SMEM_FLOATS (NSTG * STGF + 2 * TILE_S * SA + 3 * TILE_I)
#define SMEM_BYTES  (SMEM_FLOATS * 4) // 207,360 B

// tf32-rounded scratch copies of inputs
__device__ float g_x[(size_t)BB * SS * DD];
__device__ float g_wa[(size_t)II * DD];
__device__ float g_wi[(size_t)II * DD];

__device__ __forceinline__ float ex2f_(float x) {
    float y; asm("ex2.approx.f32 %0, %1;" : "=f"(y) : "f"(x)); return y;
}
__device__ __forceinline__ float rcpf_(float x) {
    float y; asm("rcp.approx.f32 %0, %1;" : "=f"(y) : "f"(x)); return y;
}
__device__ __forceinline__ float sqrtf_(float x) {
    float y; asm("sqrt.approx.f32 %0, %1;" : "=f"(y) : "f"(x)); return y;
}
__device__ __forceinline__ float sigmoidf_(float x) {
    return rcpf_(1.0f + ex2f_(-1.44269504f * x));
}
__device__ __forceinline__ float cvt_tf32(float x) {
    float y; asm("cvt.rna.tf32.f32 %0, %1;" : "=f"(y) : "f"(x)); return y;
}
__device__ __forceinline__ void cp16(uint32_t dst, const float* src) {
    asm volatile("cp.async.cg.shared.global [%0], [%1], 16;\n" :: "r"(dst), "l"(src));
}
__device__ __forceinline__ void ldsm4(uint32_t* d, uint32_t addr) {
    asm volatile("ldmatrix.sync.aligned.m8n8.x4.shared.b16 {%0,%1,%2,%3}, [%4];"
                 : "=r"(d[0]), "=r"(d[1]), "=r"(d[2]), "=r"(d[3]) : "r"(addr));
}
__device__ __forceinline__ void mma_tf32(float* c, const uint32_t* a, uint32_t b0, uint32_t b1) {
    asm volatile(
        "mma.sync.aligned.m16n8k8.row.col.f32.tf32.tf32.f32 "
        "{%0,%1,%2,%3}, {%4,%5,%6,%7}, {%8,%9}, {%0,%1,%2,%3};\n"
        : "+f"(c[0]), "+f"(c[1]), "+f"(c[2]), "+f"(c[3])
        : "r"(a[0]), "r"(a[1]), "r"(a[2]), "r"(a[3]), "r"(b0), "r"(b1));
}

// Prepass: round x, Wa, Wi to tf32 (rna), vectorized
__global__ void prepass_kernel(const float4* __restrict__ x,
                               const float4* __restrict__ wa,
                               const float4* __restrict__ wi) {
    int i = blockIdx.x * blockDim.x + threadIdx.x;  // grid covers x/4
    float4 v = x[i];
    v.x = cvt_tf32(v.x); v.y = cvt_tf32(v.y); v.z = cvt_tf32(v.z); v.w = cvt_tf32(v.w);
    ((float4*)g_x)[i] = v;
    if (i < II * DD / 4) {
        float4 a = wa[i];
        a.x = cvt_tf32(a.x); a.y = cvt_tf32(a.y); a.z = cvt_tf32(a.z); a.w = cvt_tf32(a.w);
        ((float4*)g_wa)[i] = a;
        float4 c = wi[i];
        c.x = cvt_tf32(c.x); c.y = cvt_tf32(c.y); c.z = cvt_tf32(c.z); c.w = cvt_tf32(c.w);
        ((float4*)g_wi)[i] = c;
    }
}

__global__ __launch_bounds__(512, 1)
void fused_gru_kernel(const float* __restrict__ ba,
                      const float* __restrict__ bi,
                      const float* __restrict__ gate,
                      float* __restrict__ out) {
    extern __shared__ float sm[];
    float* stages = sm;                          // [3][STGF]
    float* bpa    = sm + NSTG * STGF;            // [64][SA] raw pa -> a
    float* bpi    = bpa + TILE_S * SA;           // [64][SA] raw pi -> c
    float* al_s   = bpi + TILE_S * SA;           // [128]
    float* ba_s   = al_s + TILE_I;               // [128]
    float* bi_s   = ba_s + TILE_I;               // [128]

    const int tid  = threadIdx.x;
    const int lane = tid & 31;
    const int wid  = tid >> 5;         // 0..15
    const int gm   = wid >> 3;         // 0: pa-gemm, 1: pi-gemm
    const int wsub = wid & 7;
    const int wm   = wsub >> 2;        // 0..1 : s-offset wm*32
    const int wn   = wsub & 3;         // 0..3 : i-offset wn*32
    const int g    = lane >> 2;        // 0..7
    const int tg   = lane & 3;         // 0..3

    // ldmatrix lane addressing
    const int q  = lane >> 3;          // 0..3
    const int rr = lane & 7;           // 0..7
    const int loff = ((q & 1) * 8 + rr) * SX + (q >> 1) * 4;  // floats

    const int b  = blockIdx.x >> 4;
    const int i0 = (blockIdx.x & 15) * TILE_I;

    if (tid < TILE_I) {
        al_s[tid] = sigmoidf_(gate[i0 + tid]);
        ba_s[tid] = ba[i0 + tid];
        bi_s[tid] = bi[i0 + tid];
    }

    const float* xg = g_x + (size_t)b * SS * DD;
    const float* wg = (gm ? g_wi : g_wa) + (size_t)i0 * DD;  // this warp's W (compute)
    const float* wag = g_wa + (size_t)i0 * DD;               // loaders touch both
    const float* wig = g_wi + (size_t)i0 * DD;

    const uint32_t sm_u = (uint32_t)__cvta_generic_to_shared(sm);

    // ldmatrix byte offsets (within stage / within W block)
    const uint32_t aoff0 = (uint32_t)((wm * 32 +  0) * SX + loff) * 4;
    const uint32_t aoff1 = (uint32_t)((wm * 32 + 16) * SX + loff) * 4;
    const uint32_t boff0 = (uint32_t)((wn * 32 +  0) * SX + loff) * 4;
    const uint32_t boff1 = (uint32_t)((wn * 32 + 16) * SX + loff) * 4;
    const uint32_t wsel = (uint32_t)(XF + gm * WF) * 4;  // offset of my W block in stage

    // chunk loader
    auto issue = [&](int gcn) {
        const int stg = gcn % NSTG;
        const int s0n = (gcn >> 4) * TILE_S;
        const int k0  = (gcn & 15) * KC;
        const uint32_t sbase = sm_u + (uint32_t)(stg * STGF) * 4;
        {   // x: 64 rows x 8 float4 = 512 -> 1 per thread
            int r = tid >> 3, c4 = tid & 7;
            cp16(sbase + (uint32_t)(r * SX + c4 * 4) * 4,
                 xg + (size_t)(s0n + r) * DD + k0 + c4 * 4);
        }
#pragma unroll
        for (int j = 0; j < 2; ++j) {  // Wa/Wi: 128 rows x 8 float4 each
            int idx = tid + j * 512;
            int r = idx >> 3, c4 = idx & 7;
            size_t go = (size_t)r * DD + k0 + c4 * 4;
            uint32_t so = (uint32_t)(r * SX + c4 * 4) * 4;
            cp16(sbase + (uint32_t)XF * 4 + so, wag + go);
            cp16(sbase + (uint32_t)(XF + WF) * 4 + so, wig + go);
        }
        asm volatile("cp.async.commit_group;\n");
    };

    issue(0);
    issue(1);

    float h = 0.0f;  // scan state (tid < TILE_I)
    float acc[2][4][4];  // [mtile][ntile][frag], this warp's single gemm

    for (int st = 0; st < NST; ++st) {
#pragma unroll
        for (int mt = 0; mt < 2; ++mt)
#pragma unroll
            for (int nt = 0; nt < 4; ++nt)
#pragma unroll
                for (int f = 0; f < 4; ++f) acc[mt][nt][f] = 0.0f;

        for (int kt = 0; kt < NKT; ++kt) {
            const int gc = st * NKT + kt;

            // ensure chunk gc arrived, visible to all, then refill oldest slot
            if (gc == NCH - 1) asm volatile("cp.async.wait_group 0;\n");
            else               asm volatile("cp.async.wait_group 1;\n");
            __syncthreads();
            if (gc + 2 < NCH) issue(gc + 2);

            const int stg = gc % NSTG;
            const uint32_t xb = sm_u + (uint32_t)(stg * STGF) * 4;
            const uint32_t wb = xb + wsel;

#pragma unroll
            for (int k8 = 0; k8 < KC / 8; ++k8) {
                const uint32_t kb4 = k8 * 8 * 4;
                uint32_t af[2][4], bf[2][4];
                ldsm4(af[0], xb + aoff0 + kb4);
                ldsm4(af[1], xb + aoff1 + kb4);
                ldsm4(bf[0], wb + boff0 + kb4);  // ntiles 0,1
                ldsm4(bf[1], wb + boff1 + kb4);  // ntiles 2,3
#pragma unroll
                for (int nt = 0; nt < 4; ++nt) {
                    const int p = nt >> 1, o = nt & 1;
#pragma unroll
                    for (int mt = 0; mt < 2; ++mt)
                        mma_tf32(acc[mt][nt], af[mt], bf[p][o], bf[p][2 + o]);
                }
            }
        }

        // ---- dump raw projections: pa warps -> bpa, pi warps -> bpi ----
        float* buf = gm ? bpi : bpa;
#pragma unroll
        for (int mt = 0; mt < 2; ++mt)
#pragma unroll
            for (int nt = 0; nt < 4; ++nt)
#pragma unroll
                for (int f = 0; f < 4; ++f) {
                    int r   = wm * 32 + mt * 16 + g + ((f >= 2) ? 8 : 0);
                    int col = wn * 32 + nt * 8 + tg * 2 + (f & 1);
                    buf[r * SA + col] = acc[mt][nt][f];
                }
        __syncthreads();

        // ---- elementwise (all 512 threads) ----
#pragma unroll
        for (int e = 0; e < (TILE_S * TILE_I) / 512; ++e) {
            int idx = tid + e * 512;
            int r = idx >> 7, col = idx & 127;
            float pa = bpa[r * SA + col] + ba_s[col];
            float pi = bpi[r * SA + col] + bi_s[col];
            float rg = sigmoidf_(pa);
            float ig = sigmoidf_(pi);
            float ad = al_s[col] * ex2f_(-1.5849625007f * rg);
            float dr = sqrtf_(fmaxf(1.0f - ad * ad, 0.0f)) * (ig * pi);
            bpa[r * SA + col] = ad;
            bpi[r * SA + col] = dr;
        }
        __syncthreads();

        // ---- sequential scan (threads 0..127) ----
        if (tid < TILE_I) {
            float* op = out + ((size_t)b * SS + (size_t)st * TILE_S) * II + i0 + tid;
#pragma unroll 8
            for (int s = 0; s < TILE_S; ++s) {
                h = fmaf(bpa[s * SA + tid], h, bpi[s * SA + tid]);
                *op = h;
                op += II;
            }
        }
        // next chunk's top __syncthreads orders scan reads before next dump
    }
}

extern "C" void kernel_launch(void* const* d_in, const int* in_sizes, int n_in,
                              void* d_out, int out_size) {
    const float* x    = (const float*)d_in[0];
    const float* Wa   = (const float*)d_in[1];
    const float* ba   = (const float*)d_in[2];
    const float* Wi   = (const float*)d_in[3];
    const float* bi   = (const float*)d_in[4];
    const float* gate = (const float*)d_in[5];
    float* out = (float*)d_out;

    prepass_kernel<<<(BB * SS * DD / 4) / 256, 256>>>(
        (const float4*)x, (const float4*)Wa, (const float4*)Wi);

    cudaFuncSetAttribute(fused_gru_kernel,
                         cudaFuncAttributeMaxDynamicSharedMemorySize, SMEM_BYTES);
    fused_gru_kernel<<<BB * (II / TILE_I), 512, SMEM_BYTES>>>(ba, bi, gate, out);
}

// round 14
// speedup vs baseline: 1.5822x; 1.4915x over previous
#include <cuda_runtime.h>
#include <cuda_fp16.h>
#include <cstdint>

// Problem constants
#define BB 8
#define SS 2048
#define DD 512
#define II 2048

// Tiling
#define TILE_S 64            // s rows per CTA tile
#define TILE_I 128           // i cols per CTA
#define KC 64                // K halfs per chunk (128 B rows)
#define NKT (DD / KC)        // 8 chunks per s-tile
#define NST (SS / TILE_S)    // 32 s-tiles
#define NCH (NST * NKT)      // 256 chunks per CTA
#define NSTG 3               // cp.async pipeline stages
#define SRB 144              // smem row stride in BYTES for x/W tiles (72 halfs)
#define SA 132               // padded float stride for scan buffers

#define X_BYTES  (TILE_S * SRB)            // 9216
#define W_BYTES  (TILE_I * SRB)            // 18432
#define STG_BYTES (X_BYTES + 2 * W_BYTES)  // 46080
#define SCAN_BYTES (2 * TILE_S * SA * 4)   // 67584
#define SMEM_BYTES (NSTG * STG_BYTES + SCAN_BYTES + 3 * TILE_I * 4)  // 207360

// fp16 copies of inputs
__device__ __half g_xh[(size_t)BB * SS * DD];
__device__ __half g_wah[(size_t)II * DD];
__device__ __half g_wih[(size_t)II * DD];

__device__ __forceinline__ float ex2f_(float x) {
    float y; asm("ex2.approx.f32 %0, %1;" : "=f"(y) : "f"(x)); return y;
}
__device__ __forceinline__ float rcpf_(float x) {
    float y; asm("rcp.approx.f32 %0, %1;" : "=f"(y) : "f"(x)); return y;
}
__device__ __forceinline__ float sqrtf_(float x) {
    float y; asm("sqrt.approx.f32 %0, %1;" : "=f"(y) : "f"(x)); return y;
}
__device__ __forceinline__ float sigmoidf_(float x) {
    return rcpf_(1.0f + ex2f_(-1.44269504f * x));
}
__device__ __forceinline__ void cp16(uint32_t dst, const __half* src) {
    asm volatile("cp.async.cg.shared.global [%0], [%1], 16;\n" :: "r"(dst), "l"(src));
}
__device__ __forceinline__ void ldsm4(uint32_t* d, uint32_t addr) {
    asm volatile("ldmatrix.sync.aligned.m8n8.x4.shared.b16 {%0,%1,%2,%3}, [%4];"
                 : "=r"(d[0]), "=r"(d[1]), "=r"(d[2]), "=r"(d[3]) : "r"(addr));
}
__device__ __forceinline__ void mma_f16(float* c, const uint32_t* a, uint32_t b0, uint32_t b1) {
    asm volatile(
        "mma.sync.aligned.m16n8k16.row.col.f32.f16.f16.f32 "
        "{%0,%1,%2,%3}, {%4,%5,%6,%7}, {%8,%9}, {%0,%1,%2,%3};\n"
        : "+f"(c[0]), "+f"(c[1]), "+f"(c[2]), "+f"(c[3])
        : "r"(a[0]), "r"(a[1]), "r"(a[2]), "r"(a[3]), "r"(b0), "r"(b1));
}

// Prepass: convert x, Wa, Wi to fp16 (rn)
__global__ void prepass_kernel(const float4* __restrict__ x,
                               const float4* __restrict__ wa,
                               const float4* __restrict__ wi) {
    int i = blockIdx.x * blockDim.x + threadIdx.x;  // grid covers x/4
    float4 v = x[i];
    __half2 lo = __float22half2_rn(make_float2(v.x, v.y));
    __half2 hi = __float22half2_rn(make_float2(v.z, v.w));
    ((__half2*)g_xh)[i * 2 + 0] = lo;
    ((__half2*)g_xh)[i * 2 + 1] = hi;
    if (i < II * DD / 4) {
        float4 a = wa[i];
        ((__half2*)g_wah)[i * 2 + 0] = __float22half2_rn(make_float2(a.x, a.y));
        ((__half2*)g_wah)[i * 2 + 1] = __float22half2_rn(make_float2(a.z, a.w));
        float4 c = wi[i];
        ((__half2*)g_wih)[i * 2 + 0] = __float22half2_rn(make_float2(c.x, c.y));
        ((__half2*)g_wih)[i * 2 + 1] = __float22half2_rn(make_float2(c.z, c.w));
    }
}

__global__ __launch_bounds__(256, 1)
void fused_gru_kernel(const float* __restrict__ ba,
                      const float* __restrict__ bi,
                      const float* __restrict__ gate,
                      float* __restrict__ out) {
    extern __shared__ char smc[];
    float* a_s  = (float*)(smc + NSTG * STG_BYTES);    // [64][SA]
    float* c_s  = a_s + TILE_S * SA;                   // [64][SA]
    float* al_s = c_s + TILE_S * SA;                   // [128]
    float* ba_s = al_s + TILE_I;
    float* bi_s = ba_s + TILE_I;

    const int tid  = threadIdx.x;
    const int lane = tid & 31;
    const int w    = tid >> 5;       // 0..7
    const int wm   = w >> 2;         // 0..1 : s-offset wm*32
    const int wn   = w & 3;          // 0..3 : i-offset wn*32
    const int g    = lane >> 2;      // 0..7
    const int tg   = lane & 3;       // 0..3

    // ldmatrix lane addressing: q picks 8x8 tile, rr row within
    const int q  = lane >> 3;        // 0..3
    const int rr = lane & 7;         // 0..7
    const uint32_t loffB = (uint32_t)(((q & 1) * 8 + rr) * SRB + (q >> 1) * 16);

    const int b  = blockIdx.x >> 4;
    const int i0 = (blockIdx.x & 15) * TILE_I;

    if (tid < TILE_I) {
        al_s[tid] = sigmoidf_(gate[i0 + tid]);
        ba_s[tid] = ba[i0 + tid];
        bi_s[tid] = bi[i0 + tid];
    }

    const __half* xg  = g_xh  + (size_t)b * SS * DD;
    const __half* wag = g_wah + (size_t)i0 * DD;
    const __half* wig = g_wih + (size_t)i0 * DD;

    const uint32_t sm_u = (uint32_t)__cvta_generic_to_shared(smc);

    // ldmatrix byte offset bases within blocks
    const uint32_t aoff0 = (uint32_t)((wm * 32 +  0) * SRB) + loffB;
    const uint32_t aoff1 = (uint32_t)((wm * 32 + 16) * SRB) + loffB;
    const uint32_t boff0 = (uint32_t)((wn * 32 +  0) * SRB) + loffB;
    const uint32_t boff1 = (uint32_t)((wn * 32 + 16) * SRB) + loffB;

    // chunk loader: gcn in [0, NCH)
    auto issue = [&](int gcn) {
        const int stg = gcn % NSTG;
        const int s0n = (gcn >> 3) * TILE_S;
        const int k0  = (gcn & 7) * KC;          // halfs
        const uint32_t xb = sm_u + (uint32_t)(stg * STG_BYTES);
#pragma unroll
        for (int j = 0; j < 2; ++j) {  // x: 64 rows x 8 x 16B
            int idx = tid + j * 256;
            int r = idx >> 3, c = idx & 7;
            cp16(xb + (uint32_t)(r * SRB + c * 16),
                 xg + (size_t)(s0n + r) * DD + k0 + c * 8);
        }
#pragma unroll
        for (int j = 0; j < 4; ++j) {  // Wa/Wi: 128 rows x 8 x 16B each
            int idx = tid + j * 256;
            int r = idx >> 3, c = idx & 7;
            size_t go = (size_t)r * DD + k0 + c * 8;
            uint32_t so = (uint32_t)(r * SRB + c * 16);
            cp16(xb + X_BYTES + so, wag + go);
            cp16(xb + X_BYTES + W_BYTES + so, wig + go);
        }
        asm volatile("cp.async.commit_group;\n");
    };

    issue(0);
    issue(1);

    float h = 0.0f;  // scan state (tid < TILE_I)

    for (int st = 0; st < NST; ++st) {
        float acc[2][2][4][4];  // [gemm][mtile][ntile][frag]
#pragma unroll
        for (int gm = 0; gm < 2; ++gm)
#pragma unroll
            for (int mt = 0; mt < 2; ++mt)
#pragma unroll
                for (int nt = 0; nt < 4; ++nt)
#pragma unroll
                    for (int f = 0; f < 4; ++f) acc[gm][mt][nt][f] = 0.0f;

        for (int kt = 0; kt < NKT; ++kt) {
            const int gc = st * NKT + kt;

            if (gc == NCH - 1) asm volatile("cp.async.wait_group 0;\n");
            else               asm volatile("cp.async.wait_group 1;\n");
            __syncthreads();
            if (gc + 2 < NCH) issue(gc + 2);

            const uint32_t xb  = sm_u + (uint32_t)((gc % NSTG) * STG_BYTES);
            const uint32_t wab = xb + X_BYTES;
            const uint32_t wib = wab + W_BYTES;

#pragma unroll
            for (int ks = 0; ks < KC / 16; ++ks) {   // 4 k16 steps
                const uint32_t kb = ks * 32;         // 16 halfs = 32 B
                uint32_t af[2][4], bfa[2][4], bfi[2][4];
                ldsm4(af[0],  xb  + aoff0 + kb);
                ldsm4(af[1],  xb  + aoff1 + kb);
                ldsm4(bfa[0], wab + boff0 + kb);  // ntiles 0,1
                ldsm4(bfa[1], wab + boff1 + kb);  // ntiles 2,3
                ldsm4(bfi[0], wib + boff0 + kb);
                ldsm4(bfi[1], wib + boff1 + kb);
#pragma unroll
                for (int nt = 0; nt < 4; ++nt) {
                    const int p = nt >> 1, o = nt & 1;
#pragma unroll
                    for (int mt = 0; mt < 2; ++mt) {
                        mma_f16(acc[0][mt][nt], af[mt], bfa[p][o], bfa[p][o + 2]);
                        mma_f16(acc[1][mt][nt], af[mt], bfi[p][o], bfi[p][o + 2]);
                    }
                }
            }
        }

        // ---- in-register elementwise epilogue -> a_s/c_s ----
#pragma unroll
        for (int mt = 0; mt < 2; ++mt) {
#pragma unroll
            for (int nt = 0; nt < 4; ++nt) {
#pragma unroll
                for (int f = 0; f < 4; ++f) {
                    int r   = wm * 32 + mt * 16 + g + ((f >= 2) ? 8 : 0);
                    int col = wn * 32 + nt * 8 + tg * 2 + (f & 1);
                    float pa = acc[0][mt][nt][f] + ba_s[col];
                    float pi = acc[1][mt][nt][f] + bi_s[col];
                    float rg = sigmoidf_(pa);
                    float ig = sigmoidf_(pi);
                    float ad = al_s[col] * ex2f_(-1.5849625007f * rg);
                    float dr = sqrtf_(fmaxf(1.0f - ad * ad, 0.0f)) * (ig * pi);
                    a_s[r * SA + col] = ad;
                    c_s[r * SA + col] = dr;
                }
            }
        }
        __syncthreads();

        // ---- sequential scan (threads 0..127) ----
        if (tid < TILE_I) {
            float* op = out + ((size_t)b * SS + (size_t)st * TILE_S) * II + i0 + tid;
#pragma unroll 8
            for (int s = 0; s < TILE_S; ++s) {
                h = fmaf(a_s[s * SA + tid], h, c_s[s * SA + tid]);
                *op = h;
                op += II;
            }
        }
        // next chunk's top __syncthreads orders scan reads before next epilogue
    }
}

extern "C" void kernel_launch(void* const* d_in, const int* in_sizes, int n_in,
                              void* d_out, int out_size) {
    const float* x    = (const float*)d_in[0];
    const float* Wa   = (const float*)d_in[1];
    const float* ba   = (const float*)d_in[2];
    const float* Wi   = (const float*)d_in[3];
    const float* bi   = (const float*)d_in[4];
    const float* gate = (const float*)d_in[5];
    float* out = (float*)d_out;

    prepass_kernel<<<(BB * SS * DD / 4) / 256, 256>>>(
        (const float4*)x, (const float4*)Wa, (const float4*)Wi);

    cudaFuncSetAttribute(fused_gru_kernel,
                         cudaFuncAttributeMaxDynamicSharedMemorySize, SMEM_BYTES);
    fused_gru_kernel<<<BB * (II / TILE_I), 256, SMEM_BYTES>>>(ba, bi, gate, out);
}

// round 15
// speedup vs baseline: 1.7751x; 1.1220x over previous
#include <cuda_runtime.h>
#include <cuda_fp16.h>
#include <cstdint>

// Problem constants
#define BB 8
#define SS 2048
#define DD 512
#define II 2048

// Tiling
#define TILE_S 64            // s rows per CTA tile
#define TILE_I 128           // i cols per CTA
#define KC 64                // K halfs per chunk (128 B rows)
#define NKT (DD / KC)        // 8 chunks per s-tile
#define NST (SS / TILE_S)    // 32 s-tiles
#define NCH (NST * NKT)      // 256 chunks per CTA
#define NSTG 3               // cp.async pipeline stages
#define SRB 144              // smem row stride in BYTES for x/W tiles (72 halfs)
#define SA 132               // padded float stride for scan buffers

#define X_BYTES  (TILE_S * SRB)            // 9216
#define W_BYTES  (TILE_I * SRB)            // 18432
#define STG_BYTES (X_BYTES + 2 * W_BYTES)  // 46080
#define SCAN_BYTES (2 * TILE_S * SA * 4)   // 67584
#define SMEM_BYTES (NSTG * STG_BYTES + SCAN_BYTES + 3 * TILE_I * 4)  // 207360

// fp16 copies of inputs
__device__ __half g_xh[(size_t)BB * SS * DD];
__device__ __half g_wah[(size_t)II * DD];
__device__ __half g_wih[(size_t)II * DD];

__device__ __forceinline__ float ex2f_(float x) {
    float y; asm("ex2.approx.f32 %0, %1;" : "=f"(y) : "f"(x)); return y;
}
__device__ __forceinline__ float rcpf_(float x) {
    float y; asm("rcp.approx.f32 %0, %1;" : "=f"(y) : "f"(x)); return y;
}
__device__ __forceinline__ float sqrtf_(float x) {
    float y; asm("sqrt.approx.f32 %0, %1;" : "=f"(y) : "f"(x)); return y;
}
__device__ __forceinline__ float sigmoidf_(float x) {
    return rcpf_(1.0f + ex2f_(-1.44269504f * x));
}
__device__ __forceinline__ void cp16(uint32_t dst, const __half* src) {
    asm volatile("cp.async.cg.shared.global [%0], [%1], 16;\n" :: "r"(dst), "l"(src));
}
__device__ __forceinline__ void ldsm4(uint32_t* d, uint32_t addr) {
    asm volatile("ldmatrix.sync.aligned.m8n8.x4.shared.b16 {%0,%1,%2,%3}, [%4];"
                 : "=r"(d[0]), "=r"(d[1]), "=r"(d[2]), "=r"(d[3]) : "r"(addr));
}
__device__ __forceinline__ void mma_f16(float* c, const uint32_t* a, uint32_t b0, uint32_t b1) {
    asm volatile(
        "mma.sync.aligned.m16n8k16.row.col.f32.f16.f16.f32 "
        "{%0,%1,%2,%3}, {%4,%5,%6,%7}, {%8,%9}, {%0,%1,%2,%3};\n"
        : "+f"(c[0]), "+f"(c[1]), "+f"(c[2]), "+f"(c[3])
        : "r"(a[0]), "r"(a[1]), "r"(a[2]), "r"(a[3]), "r"(b0), "r"(b1));
}

// Prepass: convert x, Wa, Wi to fp16 (rn)
__global__ void prepass_kernel(const float4* __restrict__ x,
                               const float4* __restrict__ wa,
                               const float4* __restrict__ wi) {
    int i = blockIdx.x * blockDim.x + threadIdx.x;  // grid covers x/4
    float4 v = x[i];
    ((__half2*)g_xh)[i * 2 + 0] = __float22half2_rn(make_float2(v.x, v.y));
    ((__half2*)g_xh)[i * 2 + 1] = __float22half2_rn(make_float2(v.z, v.w));
    if (i < II * DD / 4) {
        float4 a = wa[i];
        ((__half2*)g_wah)[i * 2 + 0] = __float22half2_rn(make_float2(a.x, a.y));
        ((__half2*)g_wah)[i * 2 + 1] = __float22half2_rn(make_float2(a.z, a.w));
        float4 c = wi[i];
        ((__half2*)g_wih)[i * 2 + 0] = __float22half2_rn(make_float2(c.x, c.y));
        ((__half2*)g_wih)[i * 2 + 1] = __float22half2_rn(make_float2(c.z, c.w));
    }
}

__global__ __launch_bounds__(512, 1)
void fused_gru_kernel(const float* __restrict__ ba,
                      const float* __restrict__ bi,
                      const float* __restrict__ gate,
                      float* __restrict__ out) {
    extern __shared__ char smc[];
    float* bpa  = (float*)(smc + NSTG * STG_BYTES);    // [64][SA] raw pa -> a
    float* bpi  = bpa + TILE_S * SA;                   // [64][SA] raw pi -> c
    float* al_s = bpi + TILE_S * SA;                   // [128]
    float* ba_s = al_s + TILE_I;
    float* bi_s = ba_s + TILE_I;

    const int tid  = threadIdx.x;
    const int lane = tid & 31;
    const int wid  = tid >> 5;        // 0..15
    const int gm   = wid >> 3;        // 0: pa-gemm, 1: pi-gemm
    const int wsub = wid & 7;
    const int wm   = wsub >> 2;       // 0..1 : s-offset wm*32
    const int wn   = wsub & 3;        // 0..3 : i-offset wn*32
    const int g    = lane >> 2;       // 0..7
    const int tg   = lane & 3;        // 0..3

    // ldmatrix lane addressing: q picks 8x8 tile, rr row within
    const int q  = lane >> 3;         // 0..3
    const int rr = lane & 7;          // 0..7
    const uint32_t loffB = (uint32_t)(((q & 1) * 8 + rr) * SRB + (q >> 1) * 16);

    const int b  = blockIdx.x >> 4;
    const int i0 = (blockIdx.x & 15) * TILE_I;

    if (tid < TILE_I) {
        al_s[tid] = sigmoidf_(gate[i0 + tid]);
        ba_s[tid] = ba[i0 + tid];
        bi_s[tid] = bi[i0 + tid];
    }

    const __half* xg  = g_xh  + (size_t)b * SS * DD;
    const __half* wag = g_wah + (size_t)i0 * DD;
    const __half* wig = g_wih + (size_t)i0 * DD;

    const uint32_t sm_u = (uint32_t)__cvta_generic_to_shared(smc);

    // ldmatrix byte offset bases
    const uint32_t aoff0 = (uint32_t)((wm * 32 +  0) * SRB) + loffB;
    const uint32_t aoff1 = (uint32_t)((wm * 32 + 16) * SRB) + loffB;
    const uint32_t boff0 = (uint32_t)((wn * 32 +  0) * SRB) + loffB;
    const uint32_t boff1 = (uint32_t)((wn * 32 + 16) * SRB) + loffB;
    const uint32_t wsel  = (uint32_t)X_BYTES + (uint32_t)gm * W_BYTES;

    // chunk loader: gcn in [0, NCH); 512 threads
    auto issue = [&](int gcn) {
        const int stg = gcn % NSTG;
        const int s0n = (gcn >> 3) * TILE_S;
        const int k0  = (gcn & 7) * KC;          // halfs
        const uint32_t xb = sm_u + (uint32_t)(stg * STG_BYTES);
        {   // x: 64 rows x 8 x 16B = 512 -> 1 per thread
            int r = tid >> 3, c = tid & 7;
            cp16(xb + (uint32_t)(r * SRB + c * 16),
                 xg + (size_t)(s0n + r) * DD + k0 + c * 8);
        }
#pragma unroll
        for (int j = 0; j < 2; ++j) {  // Wa/Wi: 128 rows x 8 x 16B each
            int idx = tid + j * 512;
            int r = idx >> 3, c = idx & 7;
            size_t go = (size_t)r * DD + k0 + c * 8;
            uint32_t so = (uint32_t)(r * SRB + c * 16);
            cp16(xb + X_BYTES + so, wag + go);
            cp16(xb + X_BYTES + W_BYTES + so, wig + go);
        }
        asm volatile("cp.async.commit_group;\n");
    };

    issue(0);
    issue(1);

    float h = 0.0f;  // scan state (tid < TILE_I)
    float acc[2][4][4];  // [mtile][ntile][frag] — this warp's single gemm

    for (int st = 0; st < NST; ++st) {
#pragma unroll
        for (int mt = 0; mt < 2; ++mt)
#pragma unroll
            for (int nt = 0; nt < 4; ++nt)
#pragma unroll
                for (int f = 0; f < 4; ++f) acc[mt][nt][f] = 0.0f;

        for (int kt = 0; kt < NKT; ++kt) {
            const int gc = st * NKT + kt;

            if (gc == NCH - 1) asm volatile("cp.async.wait_group 0;\n");
            else               asm volatile("cp.async.wait_group 1;\n");
            __syncthreads();
            if (gc + 2 < NCH) issue(gc + 2);

            const uint32_t xb = sm_u + (uint32_t)((gc % NSTG) * STG_BYTES);
            const uint32_t wb = xb + wsel;

#pragma unroll
            for (int ks = 0; ks < KC / 16; ++ks) {   // 4 k16 steps
                const uint32_t kb = ks * 32;         // 16 halfs = 32 B
                uint32_t af[2][4], bf[2][4];
                ldsm4(af[0], xb + aoff0 + kb);
                ldsm4(af[1], xb + aoff1 + kb);
                ldsm4(bf[0], wb + boff0 + kb);  // ntiles 0,1
                ldsm4(bf[1], wb + boff1 + kb);  // ntiles 2,3
#pragma unroll
                for (int nt = 0; nt < 4; ++nt) {
                    const int p = nt >> 1, o = nt & 1;
#pragma unroll
                    for (int mt = 0; mt < 2; ++mt)
                        mma_f16(acc[mt][nt], af[mt], bf[p][o], bf[p][o + 2]);
                }
            }
        }

        // ---- dump raw projections: pa warps -> bpa, pi warps -> bpi ----
        float* buf = gm ? bpi : bpa;
#pragma unroll
        for (int mt = 0; mt < 2; ++mt)
#pragma unroll
            for (int nt = 0; nt < 4; ++nt)
#pragma unroll
                for (int f = 0; f < 4; ++f) {
                    int r   = wm * 32 + mt * 16 + g + ((f >= 2) ? 8 : 0);
                    int col = wn * 32 + nt * 8 + tg * 2 + (f & 1);
                    buf[r * SA + col] = acc[mt][nt][f];
                }
        __syncthreads();

        // ---- elementwise (all 512 threads, 16 elems each) ----
#pragma unroll
        for (int e = 0; e < (TILE_S * TILE_I) / 512; ++e) {
            int idx = tid + e * 512;
            int r = idx >> 7, col = idx & 127;
            float pa = bpa[r * SA + col] + ba_s[col];
            float pi = bpi[r * SA + col] + bi_s[col];
            float rg = sigmoidf_(pa);
            float ig = sigmoidf_(pi);
            float ad = al_s[col] * ex2f_(-1.5849625007f * rg);
            float dr = sqrtf_(fmaxf(1.0f - ad * ad, 0.0f)) * (ig * pi);
            bpa[r * SA + col] = ad;
            bpi[r * SA + col] = dr;
        }
        __syncthreads();

        // ---- sequential scan (threads 0..127) ----
        if (tid < TILE_I) {
            float* op = out + ((size_t)b * SS + (size_t)st * TILE_S) * II + i0 + tid;
#pragma unroll 8
            for (int s = 0; s < TILE_S; ++s) {
                h = fmaf(bpa[s * SA + tid], h, bpi[s * SA + tid]);
                *op = h;
                op += II;
            }
        }
        // next chunk's top __syncthreads orders scan reads before next dump
    }
}

extern "C" void kernel_launch(void* const* d_in, const int* in_sizes, int n_in,
                              void* d_out, int out_size) {
    const float* x    = (const float*)d_in[0];
    const float* Wa   = (const float*)d_in[1];
    const float* ba   = (const float*)d_in[2];
    const float* Wi   = (const float*)d_in[3];
    const float* bi   = (const float*)d_in[4];
    const float* gate = (const float*)d_in[5];
    float* out = (float*)d_out;

    prepass_kernel<<<(BB * SS * DD / 4) / 256, 256>>>(
        (const float4*)x, (const float4*)Wa, (const float4*)Wi);

    cudaFuncSetAttribute(fused_gru_kernel,
                         cudaFuncAttributeMaxDynamicSharedMemorySize, SMEM_BYTES);
    fused_gru_kernel<<<BB * (II / TILE_I), 512, SMEM_BYTES>>>(ba, bi, gate, out);
}

// round 16
// speedup vs baseline: 2.1312x; 1.2006x over previous
#include <cuda_runtime.h>
#include <cuda_fp16.h>
#include <cstdint>

// Problem constants
#define BB 8
#define SS 2048
#define DD 512
#define II 2048

// Tiling
#define TILE_S 64            // s rows per CTA tile
#define TILE_I 128           // i cols per CTA
#define KC 64                // K halfs per chunk (128 B per row)
#define NKT 8                // chunks per s-tile
#define NST 32               // s-tiles
#define NCH (NST * NKT)      // 256 chunks per CTA
#define NSTG 3               // pipeline stages

#define X_BYTES   (TILE_S * 128)            // 8192
#define W_BYTES   (TILE_I * 128)            // 16384
#define STG_BYTES (X_BYTES + 2 * W_BYTES)   // 40960
#define SA 132
#define SCAN_OFF  (NSTG * STG_BYTES)             // 122880
#define CONST_OFF (SCAN_OFF + 2 * TILE_S * SA * 4) // 190464
#define MBAR_OFF  (CONST_OFF + 3 * TILE_I * 4)     // 192000
#define SMEM_BYTES (MBAR_OFF + 64)                 // 192064

// fp16, chunk-contiguous, SW128-swizzled scratch layouts
// g_xh : [b][st(32)][kc(8)] -> 8192 B blocks of 64 rows x 128 B (swizzled)
// g_w*h: [it(16)][kc(8)]    -> 16384 B blocks of 128 rows x 128 B (swizzled)
__device__ __half g_xh[(size_t)BB * SS * DD];
__device__ __half g_wah[(size_t)II * DD];
__device__ __half g_wih[(size_t)II * DD];

__device__ __forceinline__ float ex2f_(float x) {
    float y; asm("ex2.approx.f32 %0, %1;" : "=f"(y) : "f"(x)); return y;
}
__device__ __forceinline__ float rcpf_(float x) {
    float y; asm("rcp.approx.f32 %0, %1;" : "=f"(y) : "f"(x)); return y;
}
__device__ __forceinline__ float sqrtf_(float x) {
    float y; asm("sqrt.approx.f32 %0, %1;" : "=f"(y) : "f"(x)); return y;
}
__device__ __forceinline__ float sigmoidf_(float x) {
    return rcpf_(1.0f + ex2f_(-1.44269504f * x));
}
__device__ __forceinline__ void ldsm4(uint32_t* d, uint32_t addr) {
    asm volatile("ldmatrix.sync.aligned.m8n8.x4.shared.b16 {%0,%1,%2,%3}, [%4];"
                 : "=r"(d[0]), "=r"(d[1]), "=r"(d[2]), "=r"(d[3]) : "r"(addr));
}
__device__ __forceinline__ void mma_f16(float* c, const uint32_t* a, uint32_t b0, uint32_t b1) {
    asm volatile(
        "mma.sync.aligned.m16n8k16.row.col.f32.f16.f16.f32 "
        "{%0,%1,%2,%3}, {%4,%5,%6,%7}, {%8,%9}, {%0,%1,%2,%3};\n"
        : "+f"(c[0]), "+f"(c[1]), "+f"(c[2]), "+f"(c[3])
        : "r"(a[0]), "r"(a[1]), "r"(a[2]), "r"(a[3]), "r"(b0), "r"(b1));
}
__device__ __forceinline__ void bulkcp(uint32_t dst, const void* src, uint32_t bytes,
                                       uint32_t mbar) {
    asm volatile(
        "cp.async.bulk.shared::cta.global.mbarrier::complete_tx::bytes [%0], [%1], %2, [%3];"
        :: "r"(dst), "l"(src), "r"(bytes), "r"(mbar) : "memory");
}
__device__ __forceinline__ void expect_tx(uint32_t mbar, uint32_t bytes) {
    asm volatile("mbarrier.arrive.expect_tx.shared.b64 _, [%0], %1;"
                 :: "r"(mbar), "r"(bytes) : "memory");
}
__device__ __forceinline__ void mbar_init(uint32_t mbar, uint32_t cnt) {
    asm volatile("mbarrier.init.shared.b64 [%0], %1;" :: "r"(mbar), "r"(cnt) : "memory");
}
__device__ __forceinline__ void bar_wait(uint32_t mbar, uint32_t phase) {
    asm volatile(
        "{\n\t.reg .pred P1;\n\t"
        "WAIT_%=:\n\t"
        "mbarrier.try_wait.parity.acquire.cta.shared::cta.b64 P1, [%0], %1, 0x989680;\n\t"
        "@P1 bra.uni DONE_%=;\n\t"
        "bra.uni WAIT_%=;\n\t"
        "DONE_%=:\n\t}"
        :: "r"(mbar), "r"(phase) : "memory");
}

// Prepass: fp16 convert + chunk-pack + SW128 swizzle into device scratch.
// 2^20 threads; each handles one 16-byte unit (8 halfs).
__global__ void prepass_kernel(const float4* __restrict__ x,
                               const float4* __restrict__ wa,
                               const float4* __restrict__ wi) {
    int u = blockIdx.x * blockDim.x + threadIdx.x;
    {
        int j = u & 7, kc = (u >> 3) & 7, s = (u >> 6) & 2047, b = u >> 17;
        int src = ((b * SS + s) * DD + kc * 64 + j * 8) >> 2;
        float4 f0 = x[src], f1 = x[src + 1];
        uint4 o; __half2 h;
        h = __float22half2_rn(make_float2(f0.x, f0.y)); o.x = *(uint32_t*)&h;
        h = __float22half2_rn(make_float2(f0.z, f0.w)); o.y = *(uint32_t*)&h;
        h = __float22half2_rn(make_float2(f1.x, f1.y)); o.z = *(uint32_t*)&h;
        h = __float22half2_rn(make_float2(f1.z, f1.w)); o.w = *(uint32_t*)&h;
        int r = s & 63;
        uint32_t cb = (uint32_t)(((b * 32 + (s >> 6)) * 8 + kc) * 8192)
                    + (uint32_t)((r * 128 + j * 16) ^ ((r & 7) << 4));
        *(uint4*)((char*)g_xh + cb) = o;
    }
    if (u < 131072) {
        int j = u & 7, kc = (u >> 3) & 7, i = u >> 6;
        int src = (i * DD + kc * 64 + j * 8) >> 2;
        int r = i & 127;
        uint32_t cb = (uint32_t)(((i >> 7) * 8 + kc) * 16384)
                    + (uint32_t)((r * 128 + j * 16) ^ ((r & 7) << 4));
        {
            float4 f0 = wa[src], f1 = wa[src + 1];
            uint4 o; __half2 h;
            h = __float22half2_rn(make_float2(f0.x, f0.y)); o.x = *(uint32_t*)&h;
            h = __float22half2_rn(make_float2(f0.z, f0.w)); o.y = *(uint32_t*)&h;
            h = __float22half2_rn(make_float2(f1.x, f1.y)); o.z = *(uint32_t*)&h;
            h = __float22half2_rn(make_float2(f1.z, f1.w)); o.w = *(uint32_t*)&h;
            *(uint4*)((char*)g_wah + cb) = o;
        }
        {
            float4 f0 = wi[src], f1 = wi[src + 1];
            uint4 o; __half2 h;
            h = __float22half2_rn(make_float2(f0.x, f0.y)); o.x = *(uint32_t*)&h;
            h = __float22half2_rn(make_float2(f0.z, f0.w)); o.y = *(uint32_t*)&h;
            h = __float22half2_rn(make_float2(f1.x, f1.y)); o.z = *(uint32_t*)&h;
            h = __float22half2_rn(make_float2(f1.z, f1.w)); o.w = *(uint32_t*)&h;
            *(uint4*)((char*)g_wih + cb) = o;
        }
    }
}

__global__ __launch_bounds__(512, 1)
void fused_gru_kernel(const float* __restrict__ ba,
                      const float* __restrict__ bi,
                      const float* __restrict__ gate,
                      float* __restrict__ out) {
    extern __shared__ char smc[];
    float* bpa  = (float*)(smc + SCAN_OFF);            // [64][SA]
    float* bpi  = bpa + TILE_S * SA;                   // [64][SA]
    float* al_s = (float*)(smc + CONST_OFF);           // [128]
    float* ba_s = al_s + TILE_I;
    float* bi_s = ba_s + TILE_I;

    const int tid  = threadIdx.x;
    const int lane = tid & 31;
    const int wid  = tid >> 5;        // 0..15
    const int gm   = wid >> 3;        // 0: pa-gemm, 1: pi-gemm
    const int wsub = wid & 7;
    const int wm   = wsub >> 2;       // 0..1 : s-offset wm*32
    const int wn   = wsub & 3;        // 0..3 : i-offset wn*32
    const int g    = lane >> 2;       // 0..7
    const int tg   = lane & 3;        // 0..3

    const int q  = lane >> 3;         // 0..3
    const int rr = lane & 7;          // 0..7
    const uint32_t rrs = (uint32_t)rr << 4;          // swizzle XOR
    const uint32_t c16 = (uint32_t)(q >> 1) << 4;    // 0 or 16

    const int b  = blockIdx.x >> 4;
    const int it = blockIdx.x & 15;
    const int i0 = it * TILE_I;

    const uint32_t sm_u = (uint32_t)__cvta_generic_to_shared(smc);

    if (tid == 0) {
        mbar_init(sm_u + MBAR_OFF + 0, 1);
        mbar_init(sm_u + MBAR_OFF + 8, 1);
        mbar_init(sm_u + MBAR_OFF + 16, 1);
    }
    if (tid < TILE_I) {
        al_s[tid] = sigmoidf_(gate[i0 + tid]);
        ba_s[tid] = ba[i0 + tid];
        bi_s[tid] = bi[i0 + tid];
    }
    __syncthreads();

    // LDSM row bases (bytes), swizzle handled by XOR on the column part
    const uint32_t rowA0 = (uint32_t)((wm * 32 + (q & 1) * 8 + rr) * 128);
    const uint32_t rowA1 = rowA0 + 16 * 128;
    const uint32_t rowB0 = (uint32_t)((wn * 32 + (q & 1) * 8 + rr) * 128);
    const uint32_t rowB1 = rowB0 + 16 * 128;
    const uint32_t wsel  = (uint32_t)X_BYTES + (uint32_t)gm * W_BYTES;

    // producer: one thread, 3 bulk copies + expect_tx per chunk
    auto issue = [&](int gcn) {
        const int s   = gcn % NSTG;
        const int stn = gcn >> 3;
        const int kc  = gcn & 7;
        const uint32_t xb = sm_u + (uint32_t)(s * STG_BYTES);
        const uint32_t mb = sm_u + MBAR_OFF + s * 8;
        expect_tx(mb, STG_BYTES);
        bulkcp(xb, (const char*)g_xh + ((size_t)((b * 32 + stn) * 8 + kc)) * 8192,
               8192, mb);
        bulkcp(xb + X_BYTES, (const char*)g_wah + ((size_t)(it * 8 + kc)) * 16384,
               16384, mb);
        bulkcp(xb + X_BYTES + W_BYTES,
               (const char*)g_wih + ((size_t)(it * 8 + kc)) * 16384, 16384, mb);
    };

    if (tid == 0) { issue(0); issue(1); }

    float h = 0.0f;  // scan state (tid < TILE_I)
    float acc[2][4][4];  // [mtile][ntile][frag] — this warp's single gemm

    for (int st = 0; st < NST; ++st) {
#pragma unroll
        for (int mt = 0; mt < 2; ++mt)
#pragma unroll
            for (int nt = 0; nt < 4; ++nt)
#pragma unroll
                for (int f = 0; f < 4; ++f) acc[mt][nt][f] = 0.0f;

        for (int kt = 0; kt < NKT; ++kt) {
            const int gc = st * NKT + kt;

            // wait for chunk gc data; then all threads past previous compute
            bar_wait(sm_u + MBAR_OFF + (gc % NSTG) * 8, (gc / NSTG) & 1);
            __syncthreads();
            if (tid == 0 && gc + 2 < NCH) issue(gc + 2);

            const uint32_t xb = sm_u + (uint32_t)((gc % NSTG) * STG_BYTES);
            const uint32_t wb = xb + wsel;

#pragma unroll
            for (int ks = 0; ks < 4; ++ks) {               // 4 k16 steps
                const uint32_t colx = (((uint32_t)ks * 32) | c16) ^ rrs;
                uint32_t af[2][4], bf[2][4];
                ldsm4(af[0], xb + rowA0 + colx);
                ldsm4(af[1], xb + rowA1 + colx);
                ldsm4(bf[0], wb + rowB0 + colx);  // ntiles 0,1
                ldsm4(bf[1], wb + rowB1 + colx);  // ntiles 2,3
#pragma unroll
                for (int nt = 0; nt < 4; ++nt) {
                    const int p = nt >> 1, o = nt & 1;
#pragma unroll
                    for (int mt = 0; mt < 2; ++mt)
                        mma_f16(acc[mt][nt], af[mt], bf[p][o], bf[p][o + 2]);
                }
            }
        }

        // ---- dump raw projections: pa warps -> bpa, pi warps -> bpi ----
        float* buf = gm ? bpi : bpa;
#pragma unroll
        for (int mt = 0; mt < 2; ++mt)
#pragma unroll
            for (int nt = 0; nt < 4; ++nt)
#pragma unroll
                for (int f = 0; f < 4; ++f) {
                    int r   = wm * 32 + mt * 16 + g + ((f >= 2) ? 8 : 0);
                    int col = wn * 32 + nt * 8 + tg * 2 + (f & 1);
                    buf[r * SA + col] = acc[mt][nt][f];
                }
        __syncthreads();

        // ---- elementwise (all 512 threads, 16 elems each) ----
#pragma unroll
        for (int e = 0; e < (TILE_S * TILE_I) / 512; ++e) {
            int idx = tid + e * 512;
            int r = idx >> 7, col = idx & 127;
            float pa = bpa[r * SA + col] + ba_s[col];
            float pi = bpi[r * SA + col] + bi_s[col];
            float rg = sigmoidf_(pa);
            float ig = sigmoidf_(pi);
            float ad = al_s[col] * ex2f_(-1.5849625007f * rg);
            float dr = sqrtf_(fmaxf(1.0f - ad * ad, 0.0f)) * (ig * pi);
            bpa[r * SA + col] = ad;
            bpi[r * SA + col] = dr;
        }
        __syncthreads();

        // ---- sequential scan (threads 0..127) ----
        if (tid < TILE_I) {
            float* op = out + ((size_t)b * SS + (size_t)st * TILE_S) * II + i0 + tid;
#pragma unroll 8
            for (int s = 0; s < TILE_S; ++s) {
                h = fmaf(bpa[s * SA + tid], h, bpi[s * SA + tid]);
                *op = h;
                op += II;
            }
        }
        // next chunk's bar_wait + __syncthreads orders scan reads before next dump
    }
}

extern "C" void kernel_launch(void* const* d_in, const int* in_sizes, int n_in,
                              void* d_out, int out_size) {
    const float* x    = (const float*)d_in[0];
    const float* Wa   = (const float*)d_in[1];
    const float* ba   = (const float*)d_in[2];
    const float* Wi   = (const float*)d_in[3];
    const float* bi   = (const float*)d_in[4];
    const float* gate = (const float*)d_in[5];
    float* out = (float*)d_out;

    prepass_kernel<<<4096, 256>>>((const float4*)x, (const float4*)Wa, (const float4*)Wi);

    cudaFuncSetAttribute(fused_gru_kernel,
                         cudaFuncAttributeMaxDynamicSharedMemorySize, SMEM_BYTES);
    fused_gru_kernel<<<BB * (II / TILE_I), 512, SMEM_BYTES>>>(ba, bi, gate, out);
}